// round 11
// baseline (speedup 1.0000x reference)
#include <cuda_runtime.h>
#include <cuda_bf16.h>
#include <cstdint>

#define KE 16
#define KD 1024
#define KF 4096
#define KT 4096
#define KA 8192
#define KSEG 4194304  /* KF*KD elements per expert matrix */

typedef __nv_bfloat16 bf16;

// ---------------- device scratch (static; no allocations) ----------------
__device__ bf16   g_w1b[(size_t)KE*KSEG];   // 128 MB ternary (exact in bf16)
__device__ bf16   g_w2b[(size_t)KE*KSEG];   // 128 MB
__device__ bf16   g_qa[(size_t)KA*KD];      // 16 MB quantized activations (gemm1 A)
__device__ bf16   g_qh[(size_t)KA*KF];      // 64 MB quantized hidden (gemm2 A)
__device__ float  g_h[(size_t)KA*KF];       // 128 MB fp32 hidden (gelu output)
__device__ float  g_wpart[4096];            // wsum partials (32 segs x 128 blocks)
__device__ float  g_wsum[32];
__device__ float  g_probs[KT*16];           // per-token softmax probs
__device__ float  g_ra[KA];
__device__ float  g_rh[KA];
__device__ float  g_ir[KT];
__device__ int    g_te[KT*2];
__device__ float  g_tw[KT*2];
__device__ int    g_cnt[KE];
__device__ int    g_off[KE];
__device__ int    g_atok[KA];
__device__ int    g_aexp[KA];
__device__ float  g_awt[KA];

__device__ __forceinline__ float rsqrt_acc(float v){
  float r = rsqrtf(v);
  r = r*(1.5f - 0.5f*v*r*r);
  return r;
}
__device__ __forceinline__ float gelu_f(float v){
  float u = 0.7978845608028654f*(v + 0.044715f*v*v*v);
  u = fminf(fmaxf(u,-15.f),15.f);
  float ez = __expf(2.f*u);
  return 0.5f*v*(1.f + (ez-1.f)/(ez+1.f));
}

// ternary quantize 16384 fp32 elems -> bf16, one block of 256 threads
__device__ __forceinline__ void wquant_chunk(const float* __restrict__ src,
                                             bf16* __restrict__ dst, int seg){
  float mean = g_wsum[seg] * (1.f/(float)KSEG);
  float sc = 1.f / fmaxf(mean, 1e-5f);
  const float4* s4 = (const float4*)src;
  ushort4* d4 = (ushort4*)dst;
  #pragma unroll 4
  for (int i=threadIdx.x; i<4096; i+=256){
    float4 v = s4[i];
    bf16 b0 = __float2bfloat16(fminf(fmaxf(rintf(v.x*sc),-1.f),1.f));
    bf16 b1 = __float2bfloat16(fminf(fmaxf(rintf(v.y*sc),-1.f),1.f));
    bf16 b2 = __float2bfloat16(fminf(fmaxf(rintf(v.z*sc),-1.f),1.f));
    bf16 b3 = __float2bfloat16(fminf(fmaxf(rintf(v.w*sc),-1.f),1.f));
    ushort4 u;
    u.x = *(unsigned short*)&b0; u.y = *(unsigned short*)&b1;
    u.z = *(unsigned short*)&b2; u.w = *(unsigned short*)&b3;
    d4[i] = u;
  }
}

// ======== prep1: wsum partials (4096 blocks) interleaved 8:1 with router ========
__global__ __launch_bounds__(256) void k_prep1(const float* __restrict__ w1,
                                               const float* __restrict__ w2,
                                               const float* __restrict__ x,
                                               const float* __restrict__ rw){
  __shared__ float sm[256];
  int idx = blockIdx.x;
  int r = idx % 9;
  if (r < 8){
    int b = (idx/9)*8 + r;              // 0..4095
    int seg = b >> 7;                   // 0..31
    int sub = b & 127;
    const float* base = (seg<16) ? (w1 + (size_t)seg*KSEG)
                                 : (w2 + (size_t)(seg-16)*KSEG);
    const float4* p = (const float4*)(base + (size_t)sub*(KSEG/128));
    float s=0.f;
    for (int i=threadIdx.x; i<KSEG/512; i+=256){
      float4 v = p[i];
      s += fabsf(v.x)+fabsf(v.y)+fabsf(v.z)+fabsf(v.w);
    }
    sm[threadIdx.x]=s; __syncthreads();
    for (int st=128; st>0; st>>=1){
      if (threadIdx.x<st) sm[threadIdx.x]+=sm[threadIdx.x+st];
      __syncthreads();
    }
    if (threadIdx.x==0) g_wpart[b]=sm[0];
  } else {
    // router: 8 warps per block, one token per warp
    int rb = idx/9;                     // 0..511
    int wid = threadIdx.x>>5, lane = threadIdx.x&31;
    int t = rb*8 + wid;
    const float* xr = x + (size_t)t*KD;
    float acc[16]; float ss=0.f;
    #pragma unroll
    for (int e=0;e<16;e++) acc[e]=0.f;
    #pragma unroll 1
    for (int j=0;j<8;j++){
      int k = j*128 + lane*4;
      float4 xv = *(const float4*)(xr + k);
      ss += xv.x*xv.x+xv.y*xv.y+xv.z*xv.z+xv.w*xv.w;
      #pragma unroll
      for (int e=0;e<16;e++){
        float4 wv = __ldg((const float4*)(rw + e*KD + k));
        acc[e] += xv.x*wv.x+xv.y*wv.y+xv.z*wv.z+xv.w*wv.w;
      }
    }
    #pragma unroll
    for (int o=16;o>0;o>>=1){
      ss += __shfl_xor_sync(~0u, ss, o);
      #pragma unroll
      for (int e=0;e<16;e++) acc[e] += __shfl_xor_sync(~0u, acc[e], o);
    }
    if (lane==0){
      g_ir[t] = rsqrt_acc(ss*(1.f/(float)KD) + 1e-6f);
      float m = acc[0];
      #pragma unroll
      for (int e=1;e<16;e++) m = fmaxf(m, acc[e]);
      float p[16]; float Z=0.f;
      #pragma unroll
      for (int e=0;e<16;e++){ p[e]=__expf(acc[e]-m); Z+=p[e]; }
      float invZ = 1.f/Z;
      #pragma unroll
      for (int e=0;e<16;e++){ p[e]*=invZ; g_probs[t*16+e]=p[e]; }
      int i0=0;
      for (int e=1;e<16;e++) if (p[e]>p[i0]) i0=e;
      int i1=(i0==0)?1:0;
      for (int e=0;e<16;e++){ if (e!=i0 && p[e]>p[i1]) i1=e; }
      float s2 = p[i0]+p[i1]+1e-8f;
      g_te[2*t]=i0; g_te[2*t+1]=i1;
      g_tw[2*t]=p[i0]/s2; g_tw[2*t+1]=p[i1]/s2;
    }
  }
}

// ======== mid: reduce wsum, aux loss, offsets, scatter (one block) ========
__global__ void k_mid(float* out_aux){
  __shared__ float sps[16];
  __shared__ int scnt[16], soff[16], scur[16];
  int tid = threadIdx.x;            // 1024
  if (tid<16){ sps[tid]=0.f; scnt[tid]=0; scur[tid]=0; }
  if (tid<32){
    float s=0.f;
    for (int i=0;i<128;i++) s += g_wpart[tid*128+i];
    g_wsum[tid]=s;
  }
  __syncthreads();
  {
    float lp[16];
    #pragma unroll
    for (int e=0;e<16;e++) lp[e]=0.f;
    for (int t=tid;t<KT;t+=1024){
      #pragma unroll
      for (int e=0;e<16;e++) lp[e] += g_probs[t*16+e];
    }
    #pragma unroll
    for (int e=0;e<16;e++) atomicAdd(&sps[e], lp[e]);
  }
  for (int i=tid;i<KA;i+=1024) atomicAdd(&scnt[g_te[i]], 1);
  __syncthreads();
  if (tid==0){
    int off=0;
    float aux=0.f;
    for (int e=0;e<16;e++){
      soff[e]=off; g_off[e]=off; g_cnt[e]=scnt[e]; off+=scnt[e];
      aux += ((float)scnt[e]/(float)KA) * (sps[e]/(float)KT);
    }
    *out_aux = 16.f*aux;
  }
  __syncthreads();
  for (int t=tid;t<KT;t+=1024){
    #pragma unroll
    for (int s=0;s<2;s++){
      int e = g_te[2*t+s];
      int pos = soff[e] + atomicAdd(&scur[e],1);
      g_atok[pos]=t; g_aexp[pos]=e; g_awt[pos]=g_tw[2*t+s];
    }
  }
}

// ======== prep2: wquant(w1) [4096 blocks] + qa [8192 blocks] ========
__global__ __launch_bounds__(256) void k_prep2(const float* __restrict__ w1,
                                               const float* __restrict__ x,
                                               const float* __restrict__ g1){
  __shared__ float sm[256];
  int b = blockIdx.x;
  if (b < 4096){
    wquant_chunk(w1 + (size_t)b*16384, g_w1b + (size_t)b*16384, b>>8);
    return;
  }
  int a = b - 4096;
  int tid = threadIdx.x;
  int t = g_atok[a], e = g_aexp[a];
  float ir = g_ir[t];
  float4 xv = *(const float4*)(x  + (size_t)t*KD + tid*4);
  float4 gv = *(const float4*)(g1 + (size_t)e*KD + tid*4);
  float4 y = make_float4(xv.x*gv.x*ir, xv.y*gv.y*ir, xv.z*gv.z*ir, xv.w*gv.w*ir);
  float mx = fmaxf(fmaxf(fabsf(y.x),fabsf(y.y)),fmaxf(fabsf(y.z),fabsf(y.w)));
  sm[tid]=mx; __syncthreads();
  for (int st=128;st>0;st>>=1){
    if (tid<st) sm[tid]=fmaxf(sm[tid],sm[tid+st]);
    __syncthreads();
  }
  float mv = fmaxf(sm[0],1e-5f);
  float sc = 127.f/mv;
  if (tid==0) g_ra[a] = mv*(1.f/127.f);
  float q0=fminf(fmaxf(rintf(y.x*sc),-128.f),127.f);
  float q1=fminf(fmaxf(rintf(y.y*sc),-128.f),127.f);
  float q2=fminf(fmaxf(rintf(y.z*sc),-128.f),127.f);
  float q3=fminf(fmaxf(rintf(y.w*sc),-128.f),127.f);
  bf16 b0=__float2bfloat16(q0), b1=__float2bfloat16(q1);
  bf16 b2=__float2bfloat16(q2), b3=__float2bfloat16(q3);
  ushort4 u;
  u.x=*(unsigned short*)&b0; u.y=*(unsigned short*)&b1;
  u.z=*(unsigned short*)&b2; u.w=*(unsigned short*)&b3;
  *(ushort4*)(g_qa + (size_t)a*KD + tid*4) = u;
}

// ======== rmsnorm(h,g2[e]) + act_quant -> qh ========
__global__ void k_hq(const float* __restrict__ g2){
  int a = blockIdx.x; int tid=threadIdx.x;
  int e = g_aexp[a];
  const float* hr = g_h + (size_t)a*KF;
  float4 y[4]; float ss=0.f, mx=0.f;
  #pragma unroll
  for (int j=0;j<4;j++){
    int k = tid*4 + j*1024;
    float4 hv = *(const float4*)(hr + k);
    float4 gv = *(const float4*)(g2 + (size_t)e*KF + k);
    ss += hv.x*hv.x+hv.y*hv.y+hv.z*hv.z+hv.w*hv.w;
    y[j] = make_float4(hv.x*gv.x, hv.y*gv.y, hv.z*gv.z, hv.w*gv.w);
    mx = fmaxf(mx, fmaxf(fmaxf(fabsf(y[j].x),fabsf(y[j].y)),
                         fmaxf(fabsf(y[j].z),fabsf(y[j].w))));
  }
  __shared__ float sms[256], smm[256];
  sms[tid]=ss; smm[tid]=mx; __syncthreads();
  for (int st=128;st>0;st>>=1){
    if (tid<st){ sms[tid]+=sms[tid+st]; smm[tid]=fmaxf(smm[tid],smm[tid+st]); }
    __syncthreads();
  }
  float ir = rsqrt_acc(sms[0]*(1.f/(float)KF)+1e-6f);
  float my = fmaxf(smm[0]*ir, 1e-5f);
  float sc = 127.f/my;
  if (tid==0) g_rh[a] = my*(1.f/127.f);
  float f = ir*sc;
  #pragma unroll
  for (int j=0;j<4;j++){
    int k = tid*4 + j*1024;
    float q0=fminf(fmaxf(rintf(y[j].x*f),-128.f),127.f);
    float q1=fminf(fmaxf(rintf(y[j].y*f),-128.f),127.f);
    float q2=fminf(fmaxf(rintf(y[j].z*f),-128.f),127.f);
    float q3=fminf(fmaxf(rintf(y[j].w*f),-128.f),127.f);
    bf16 b0=__float2bfloat16(q0), b1=__float2bfloat16(q1);
    bf16 b2=__float2bfloat16(q2), b3=__float2bfloat16(q3);
    ushort4 u;
    u.x=*(unsigned short*)&b0; u.y=*(unsigned short*)&b1;
    u.z=*(unsigned short*)&b2; u.w=*(unsigned short*)&b3;
    *(ushort4*)(g_qh + (size_t)a*KF + k)=u;
  }
}

// ======== pipelined bf16 HMMA GEMM tile (proven R10 body) ========
#define CP16(dst, src, sz) \
  asm volatile("cp.async.cg.shared.global [%0],[%1],16,%2;\n"::"r"(dst),"l"(src),"r"(sz))
#define CP_COMMIT() asm volatile("cp.async.commit_group;\n"::)
#define CP_WAIT2()  asm volatile("cp.async.wait_group 2;\n"::: "memory")
#define LDSM4(r0,r1,r2,r3,addr) \
  asm volatile("ldmatrix.sync.aligned.m8n8.x4.shared.b16 {%0,%1,%2,%3},[%4];\n" \
    : "=r"(r0),"=r"(r1),"=r"(r2),"=r"(r3) : "r"(addr))

#define DSMEM (3*32768)

template<bool G1, int KDIM, int NDIM>
__device__ __forceinline__ void gemm_tile(int e, int mtile, int ntile,
                                          float* __restrict__ out, char* dynsm){
  int cnt = g_cnt[e];
  int m0 = mtile*128;
  if (m0 >= cnt) return;
  int n0 = ntile*128;
  int off = g_off[e];
  const bf16* A = G1 ? g_qa : g_qh;
  const bf16* B = (G1 ? g_w1b : g_w2b) + (size_t)e*KSEG;

  uint32_t sbase = (uint32_t)__cvta_generic_to_shared(dynsm);

  int tid = threadIdx.x, wid = tid>>5, lane = tid&31;
  int wm = wid&3, wn = wid>>2;

  int lr = tid>>1;
  int lcb = (tid&1)*4;
  int swr = lr&7;
  int mA = m0 + lr;
  int szA = (mA < cnt) ? 16 : 0;
  const bf16* gA = A + (size_t)(off + min(mA, cnt-1))*KDIM;
  const bf16* gB = B + (size_t)(n0 + lr)*KDIM;
  uint32_t rowoff = (uint32_t)lr*128;

  uint32_t rAoff[2]; int rAsw[2];
  #pragma unroll
  for (int mf=0;mf<2;mf++){
    int rr = wm*32 + mf*16 + (lane&15);
    rAoff[mf] = (uint32_t)rr*128; rAsw[mf] = rr&7;
  }
  int aHi = lane>>4;
  uint32_t rBoff[4]; int rBsw[4];
  #pragma unroll
  for (int p=0;p<4;p++){
    int rr = wn*64 + p*16 + (lane&7) + ((lane>>4)<<3);
    rBoff[p] = (uint32_t)rr*128; rBsw[p] = rr&7;
  }
  int bHi = (lane>>3)&1;

  float c[2][8][4];
  #pragma unroll
  for (int i=0;i<2;i++)
    #pragma unroll
    for (int j=0;j<8;j++)
      #pragma unroll
      for (int k=0;k<4;k++) c[i][j][k]=0.f;

  const int NK = KDIM/64;
  #pragma unroll
  for (int s=0;s<2;s++){
    size_t k0 = (size_t)s*64;
    uint32_t ab = sbase + s*32768;
    #pragma unroll
    for (int j=0;j<4;j++){
      int ch = lcb + j;
      uint32_t doff = rowoff + (uint32_t)((ch ^ swr)<<4);
      CP16(ab + doff,          gA + k0 + ch*8, szA);
      CP16(ab + 16384 + doff,  gB + k0 + ch*8, 16);
    }
    CP_COMMIT();
  }

  for (int kt=0; kt<NK; kt++){
    if (kt+2 < NK){
      int s = (kt+2)%3;
      size_t k0 = (size_t)(kt+2)*64;
      uint32_t ab = sbase + s*32768;
      #pragma unroll
      for (int j=0;j<4;j++){
        int ch = lcb + j;
        uint32_t doff = rowoff + (uint32_t)((ch ^ swr)<<4);
        CP16(ab + doff,          gA + k0 + ch*8, szA);
        CP16(ab + 16384 + doff,  gB + k0 + ch*8, 16);
      }
    }
    CP_COMMIT();
    CP_WAIT2();
    __syncthreads();

    uint32_t ab = sbase + (kt%3)*32768;
    uint32_t bb = ab + 16384;
    #pragma unroll
    for (int ks=0;ks<4;ks++){
      int a[2][4];
      #pragma unroll
      for (int mf=0;mf<2;mf++){
        uint32_t addr = ab + rAoff[mf] + (uint32_t)(((2*ks + aHi) ^ rAsw[mf])<<4);
        LDSM4(a[mf][0],a[mf][1],a[mf][2],a[mf][3], addr);
      }
      int b[4][4];
      #pragma unroll
      for (int p=0;p<4;p++){
        uint32_t addr = bb + rBoff[p] + (uint32_t)(((2*ks + bHi) ^ rBsw[p])<<4);
        LDSM4(b[p][0],b[p][1],b[p][2],b[p][3], addr);
      }
      #pragma unroll
      for (int p=0;p<4;p++){
        #pragma unroll
        for (int half=0;half<2;half++){
          int nf = 2*p + half;
          int bb0 = b[p][half*2+0], bb1 = b[p][half*2+1];
          #pragma unroll
          for (int mf=0;mf<2;mf++){
            asm volatile(
              "mma.sync.aligned.m16n8k16.row.col.f32.bf16.bf16.f32 "
              "{%0,%1,%2,%3},{%4,%5,%6,%7},{%8,%9},{%0,%1,%2,%3};\n"
              : "+f"(c[mf][nf][0]),"+f"(c[mf][nf][1]),
                "+f"(c[mf][nf][2]),"+f"(c[mf][nf][3])
              : "r"(a[mf][0]),"r"(a[mf][1]),"r"(a[mf][2]),"r"(a[mf][3]),
                "r"(bb0),"r"(bb1));
          }
        }
      }
    }
    __syncthreads();
  }

  int gid = lane>>2, tig = lane&3;
  float wmean = fmaxf(g_wsum[G1 ? e : 16+e]*(1.f/(float)KSEG), 1e-5f);
  #pragma unroll
  for (int mf=0;mf<2;mf++){
    #pragma unroll
    for (int h2=0;h2<2;h2++){
      int m = m0 + wm*32 + mf*16 + gid + h2*8;
      if (m >= cnt) continue;
      int arow = off + m;
      float sc = (G1 ? g_ra[arow] : g_rh[arow]) * wmean;
      if (G1){
        float* orow = g_h + (size_t)arow*NDIM;
        #pragma unroll
        for (int nf=0;nf<8;nf++){
          int col = n0 + wn*64 + nf*8 + 2*tig;
          float v0 = gelu_f(c[mf][nf][h2*2+0]*sc);
          float v1 = gelu_f(c[mf][nf][h2*2+1]*sc);
          *(float2*)(orow + col) = make_float2(v0,v1);
        }
      } else {
        sc *= g_awt[arow];
        int tok = g_atok[arow];
        float* orow = out + (size_t)tok*NDIM;
        #pragma unroll
        for (int nf=0;nf<8;nf++){
          int col = n0 + wn*64 + nf*8 + 2*tig;
          atomicAdd(orow + col,     c[mf][nf][h2*2+0]*sc);
          atomicAdd(orow + col + 1, c[mf][nf][h2*2+1]*sc);
        }
      }
    }
  }
}

// ======== g1w2: gemm1 tiles (16384 logical) interleaved 4:1 with wquant(w2) ========
__global__ __launch_bounds__(256,2) void k_g1w2(const float* __restrict__ w2){
  extern __shared__ char dynsm[];
  int idx = blockIdx.x;
  int q = idx/5, r = idx%5;
  if (r == 4){
    wquant_chunk(w2 + (size_t)q*16384, g_w2b + (size_t)q*16384, 16 + (q>>8));
    return;
  }
  int g = q*4 + r;                 // 0..16383
  int ntile = g & 31, mtile = (g>>5)&31, e = g>>10;
  gemm_tile<true, KD, KF>(e, mtile, ntile, nullptr, dynsm);
}

// ======== gemm2: flat grid 8n x 32m x 16e = 4096 ========
__global__ __launch_bounds__(256,2) void k_gemm2f(float* __restrict__ out){
  extern __shared__ char dynsm[];
  int g = blockIdx.x;
  int ntile = g & 7, mtile = (g>>3)&31, e = g>>8;
  gemm_tile<false, KF, KD>(e, mtile, ntile, out, dynsm);
}

extern "C" void kernel_launch(void* const* d_in, const int* in_sizes, int n_in,
                              void* d_out, int out_size){
  (void)in_sizes; (void)n_in;
  const float* x  = (const float*)d_in[0];
  const float* rw = (const float*)d_in[1];
  const float* w1 = (const float*)d_in[2];
  const float* g1 = (const float*)d_in[3];
  const float* w2 = (const float*)d_in[4];
  const float* g2 = (const float*)d_in[5];
  float* out = (float*)d_out;

  cudaFuncSetAttribute(k_g1w2,
                       cudaFuncAttributeMaxDynamicSharedMemorySize, DSMEM);
  cudaFuncSetAttribute(k_gemm2f,
                       cudaFuncAttributeMaxDynamicSharedMemorySize, DSMEM);

  cudaMemsetAsync(out, 0, (size_t)out_size*sizeof(float));
  k_prep1<<<4608,256>>>(w1,w2,x,rw);
  k_mid<<<1,1024>>>(out + (size_t)out_size - 1);
  k_prep2<<<12288,256>>>(w1,x,g1);
  k_g1w2<<<20480,256,DSMEM>>>(w2);
  k_hq<<<KA,256>>>(g2);
  k_gemm2f<<<4096,256,DSMEM>>>(out);
}

// round 12
// speedup vs baseline: 1.0127x; 1.0127x over previous
#include <cuda_runtime.h>
#include <cuda_bf16.h>
#include <cstdint>

#define KE 16
#define KD 1024
#define KF 4096
#define KT 4096
#define KA 8192
#define KSEG 4194304  /* KF*KD elements per expert matrix */

typedef __nv_bfloat16 bf16;

// ---------------- device scratch (static; no allocations) ----------------
__device__ bf16   g_w1b[(size_t)KE*KSEG];   // 128 MB ternary (exact in bf16)
__device__ bf16   g_w2b[(size_t)KE*KSEG];   // 128 MB
__device__ bf16   g_qa[(size_t)KA*KD];      // 16 MB quantized activations (gemm1 A)
__device__ bf16   g_qh[(size_t)KA*KF];      // 64 MB quantized hidden (gemm2 A)
__device__ float  g_h[(size_t)KA*KF];       // 128 MB fp32 hidden (gelu output)
__device__ float  g_wpart[4096];            // wsum partials (32 segs x 128 blocks)
__device__ float  g_wsum[32];
__device__ float  g_probs[KT*16];           // per-token softmax probs
__device__ float  g_ra[KA];
__device__ float  g_rh[KA];
__device__ float  g_ir[KT];
__device__ int    g_te[KT*2];
__device__ float  g_tw[KT*2];
__device__ int    g_cnt[KE];
__device__ int    g_off[KE];
__device__ int    g_atok[KA];
__device__ int    g_aexp[KA];
__device__ float  g_awt[KA];

__device__ __forceinline__ float rsqrt_acc(float v){
  float r = rsqrtf(v);
  r = r*(1.5f - 0.5f*v*r*r);
  return r;
}
__device__ __forceinline__ float gelu_f(float v){
  float u = 0.7978845608028654f*(v + 0.044715f*v*v*v);
  u = fminf(fmaxf(u,-15.f),15.f);
  float ez = __expf(2.f*u);
  return 0.5f*v*(1.f + (ez-1.f)/(ez+1.f));
}

// ternary quantize 16384 fp32 elems -> bf16, one block of 256 threads
__device__ __forceinline__ void wquant_chunk(const float* __restrict__ src,
                                             bf16* __restrict__ dst, int seg){
  float mean = g_wsum[seg] * (1.f/(float)KSEG);
  float sc = 1.f / fmaxf(mean, 1e-5f);
  const float4* s4 = (const float4*)src;
  ushort4* d4 = (ushort4*)dst;
  #pragma unroll 4
  for (int i=threadIdx.x; i<4096; i+=256){
    float4 v = s4[i];
    bf16 b0 = __float2bfloat16(fminf(fmaxf(rintf(v.x*sc),-1.f),1.f));
    bf16 b1 = __float2bfloat16(fminf(fmaxf(rintf(v.y*sc),-1.f),1.f));
    bf16 b2 = __float2bfloat16(fminf(fmaxf(rintf(v.z*sc),-1.f),1.f));
    bf16 b3 = __float2bfloat16(fminf(fmaxf(rintf(v.w*sc),-1.f),1.f));
    ushort4 u;
    u.x = *(unsigned short*)&b0; u.y = *(unsigned short*)&b1;
    u.z = *(unsigned short*)&b2; u.w = *(unsigned short*)&b3;
    d4[i] = u;
  }
}

// ======== prep1: wsum partials (4096 blocks) interleaved 8:1 with router ========
__global__ __launch_bounds__(256) void k_prep1(const float* __restrict__ w1,
                                               const float* __restrict__ w2,
                                               const float* __restrict__ x,
                                               const float* __restrict__ rw){
  __shared__ float sm[256];
  int idx = blockIdx.x;
  int r = idx % 9;
  if (r < 8){
    int b = (idx/9)*8 + r;              // 0..4095
    int seg = b >> 7;                   // 0..31
    int sub = b & 127;
    const float* base = (seg<16) ? (w1 + (size_t)seg*KSEG)
                                 : (w2 + (size_t)(seg-16)*KSEG);
    const float4* p = (const float4*)(base + (size_t)sub*(KSEG/128));
    float s=0.f;
    for (int i=threadIdx.x; i<KSEG/512; i+=256){
      float4 v = p[i];
      s += fabsf(v.x)+fabsf(v.y)+fabsf(v.z)+fabsf(v.w);
    }
    sm[threadIdx.x]=s; __syncthreads();
    for (int st=128; st>0; st>>=1){
      if (threadIdx.x<st) sm[threadIdx.x]+=sm[threadIdx.x+st];
      __syncthreads();
    }
    if (threadIdx.x==0) g_wpart[b]=sm[0];
  } else {
    // router: 8 warps per block, one token per warp
    int rb = idx/9;                     // 0..511
    int wid = threadIdx.x>>5, lane = threadIdx.x&31;
    int t = rb*8 + wid;
    const float* xr = x + (size_t)t*KD;
    float acc[16]; float ss=0.f;
    #pragma unroll
    for (int e=0;e<16;e++) acc[e]=0.f;
    #pragma unroll 1
    for (int j=0;j<8;j++){
      int k = j*128 + lane*4;
      float4 xv = *(const float4*)(xr + k);
      ss += xv.x*xv.x+xv.y*xv.y+xv.z*xv.z+xv.w*xv.w;
      #pragma unroll
      for (int e=0;e<16;e++){
        float4 wv = __ldg((const float4*)(rw + e*KD + k));
        acc[e] += xv.x*wv.x+xv.y*wv.y+xv.z*wv.z+xv.w*wv.w;
      }
    }
    #pragma unroll
    for (int o=16;o>0;o>>=1){
      ss += __shfl_xor_sync(~0u, ss, o);
      #pragma unroll
      for (int e=0;e<16;e++) acc[e] += __shfl_xor_sync(~0u, acc[e], o);
    }
    if (lane==0){
      g_ir[t] = rsqrt_acc(ss*(1.f/(float)KD) + 1e-6f);
      float m = acc[0];
      #pragma unroll
      for (int e=1;e<16;e++) m = fmaxf(m, acc[e]);
      float p[16]; float Z=0.f;
      #pragma unroll
      for (int e=0;e<16;e++){ p[e]=__expf(acc[e]-m); Z+=p[e]; }
      float invZ = 1.f/Z;
      #pragma unroll
      for (int e=0;e<16;e++){ p[e]*=invZ; g_probs[t*16+e]=p[e]; }
      int i0=0;
      for (int e=1;e<16;e++) if (p[e]>p[i0]) i0=e;
      int i1=(i0==0)?1:0;
      for (int e=0;e<16;e++){ if (e!=i0 && p[e]>p[i1]) i1=e; }
      float s2 = p[i0]+p[i1]+1e-8f;
      g_te[2*t]=i0; g_te[2*t+1]=i1;
      g_tw[2*t]=p[i0]/s2; g_tw[2*t+1]=p[i1]/s2;
    }
  }
}

// ======== mid: reduce wsum, aux loss, offsets, scatter (one block) ========
__global__ void k_mid(float* out_aux){
  __shared__ float sps[16];
  __shared__ int scnt[16], soff[16], scur[16];
  int tid = threadIdx.x;            // 1024
  if (tid<16){ sps[tid]=0.f; scnt[tid]=0; scur[tid]=0; }
  if (tid<32){
    float s=0.f;
    for (int i=0;i<128;i++) s += g_wpart[tid*128+i];
    g_wsum[tid]=s;
  }
  __syncthreads();
  {
    float lp[16];
    #pragma unroll
    for (int e=0;e<16;e++) lp[e]=0.f;
    for (int t=tid;t<KT;t+=1024){
      #pragma unroll
      for (int e=0;e<16;e++) lp[e] += g_probs[t*16+e];
    }
    #pragma unroll
    for (int e=0;e<16;e++) atomicAdd(&sps[e], lp[e]);
  }
  for (int i=tid;i<KA;i+=1024) atomicAdd(&scnt[g_te[i]], 1);
  __syncthreads();
  if (tid==0){
    int off=0;
    float aux=0.f;
    for (int e=0;e<16;e++){
      soff[e]=off; g_off[e]=off; g_cnt[e]=scnt[e]; off+=scnt[e];
      aux += ((float)scnt[e]/(float)KA) * (sps[e]/(float)KT);
    }
    *out_aux = 16.f*aux;
  }
  __syncthreads();
  for (int t=tid;t<KT;t+=1024){
    #pragma unroll
    for (int s=0;s<2;s++){
      int e = g_te[2*t+s];
      int pos = soff[e] + atomicAdd(&scur[e],1);
      g_atok[pos]=t; g_aexp[pos]=e; g_awt[pos]=g_tw[2*t+s];
    }
  }
}

// ======== prep2: wquant(w1) [4096] + wquant(w2) [4096] + qa [8192] ========
__global__ __launch_bounds__(256) void k_prep2(const float* __restrict__ w1,
                                               const float* __restrict__ w2,
                                               const float* __restrict__ x,
                                               const float* __restrict__ g1){
  __shared__ float sm[256];
  int b = blockIdx.x;
  if (b < 4096){
    wquant_chunk(w1 + (size_t)b*16384, g_w1b + (size_t)b*16384, b>>8);
    return;
  }
  if (b < 8192){
    int q = b - 4096;
    wquant_chunk(w2 + (size_t)q*16384, g_w2b + (size_t)q*16384, 16 + (q>>8));
    return;
  }
  int a = b - 8192;
  int tid = threadIdx.x;
  int t = g_atok[a], e = g_aexp[a];
  float ir = g_ir[t];
  float4 xv = *(const float4*)(x  + (size_t)t*KD + tid*4);
  float4 gv = *(const float4*)(g1 + (size_t)e*KD + tid*4);
  float4 y = make_float4(xv.x*gv.x*ir, xv.y*gv.y*ir, xv.z*gv.z*ir, xv.w*gv.w*ir);
  float mx = fmaxf(fmaxf(fabsf(y.x),fabsf(y.y)),fmaxf(fabsf(y.z),fabsf(y.w)));
  sm[tid]=mx; __syncthreads();
  for (int st=128;st>0;st>>=1){
    if (tid<st) sm[tid]=fmaxf(sm[tid],sm[tid+st]);
    __syncthreads();
  }
  float mv = fmaxf(sm[0],1e-5f);
  float sc = 127.f/mv;
  if (tid==0) g_ra[a] = mv*(1.f/127.f);
  float q0=fminf(fmaxf(rintf(y.x*sc),-128.f),127.f);
  float q1=fminf(fmaxf(rintf(y.y*sc),-128.f),127.f);
  float q2=fminf(fmaxf(rintf(y.z*sc),-128.f),127.f);
  float q3=fminf(fmaxf(rintf(y.w*sc),-128.f),127.f);
  bf16 b0=__float2bfloat16(q0), b1=__float2bfloat16(q1);
  bf16 b2=__float2bfloat16(q2), b3=__float2bfloat16(q3);
  ushort4 u;
  u.x=*(unsigned short*)&b0; u.y=*(unsigned short*)&b1;
  u.z=*(unsigned short*)&b2; u.w=*(unsigned short*)&b3;
  *(ushort4*)(g_qa + (size_t)a*KD + tid*4) = u;
}

// ======== rmsnorm(h,g2[e]) + act_quant -> qh ========
__global__ void k_hq(const float* __restrict__ g2){
  int a = blockIdx.x; int tid=threadIdx.x;
  int e = g_aexp[a];
  const float* hr = g_h + (size_t)a*KF;
  float4 y[4]; float ss=0.f, mx=0.f;
  #pragma unroll
  for (int j=0;j<4;j++){
    int k = tid*4 + j*1024;
    float4 hv = *(const float4*)(hr + k);
    float4 gv = *(const float4*)(g2 + (size_t)e*KF + k);
    ss += hv.x*hv.x+hv.y*hv.y+hv.z*hv.z+hv.w*hv.w;
    y[j] = make_float4(hv.x*gv.x, hv.y*gv.y, hv.z*gv.z, hv.w*gv.w);
    mx = fmaxf(mx, fmaxf(fmaxf(fabsf(y[j].x),fabsf(y[j].y)),
                         fmaxf(fabsf(y[j].z),fabsf(y[j].w))));
  }
  __shared__ float sms[256], smm[256];
  sms[tid]=ss; smm[tid]=mx; __syncthreads();
  for (int st=128;st>0;st>>=1){
    if (tid<st){ sms[tid]+=sms[tid+st]; smm[tid]=fmaxf(smm[tid],smm[tid+st]); }
    __syncthreads();
  }
  float ir = rsqrt_acc(sms[0]*(1.f/(float)KF)+1e-6f);
  float my = fmaxf(smm[0]*ir, 1e-5f);
  float sc = 127.f/my;
  if (tid==0) g_rh[a] = my*(1.f/127.f);
  float f = ir*sc;
  #pragma unroll
  for (int j=0;j<4;j++){
    int k = tid*4 + j*1024;
    float q0=fminf(fmaxf(rintf(y[j].x*f),-128.f),127.f);
    float q1=fminf(fmaxf(rintf(y[j].y*f),-128.f),127.f);
    float q2=fminf(fmaxf(rintf(y[j].z*f),-128.f),127.f);
    float q3=fminf(fmaxf(rintf(y[j].w*f),-128.f),127.f);
    bf16 b0=__float2bfloat16(q0), b1=__float2bfloat16(q1);
    bf16 b2=__float2bfloat16(q2), b3=__float2bfloat16(q3);
    ushort4 u;
    u.x=*(unsigned short*)&b0; u.y=*(unsigned short*)&b1;
    u.z=*(unsigned short*)&b2; u.w=*(unsigned short*)&b3;
    *(ushort4*)(g_qh + (size_t)a*KF + k)=u;
  }
}

// ======== pipelined bf16 HMMA GEMM, single barrier per K-step ========
#define CP16(dst, src, sz) \
  asm volatile("cp.async.cg.shared.global [%0],[%1],16,%2;\n"::"r"(dst),"l"(src),"r"(sz))
#define CP_COMMIT() asm volatile("cp.async.commit_group;\n"::)
#define CP_WAIT1()  asm volatile("cp.async.wait_group 1;\n"::: "memory")
#define LDSM4(r0,r1,r2,r3,addr) \
  asm volatile("ldmatrix.sync.aligned.m8n8.x4.shared.b16 {%0,%1,%2,%3},[%4];\n" \
    : "=r"(r0),"=r"(r1),"=r"(r2),"=r"(r3) : "r"(addr))

#define DSMEM (3*32768)

template<bool G1, int KDIM, int NDIM>
__global__ __launch_bounds__(256,2) void k_gemm(float* __restrict__ out){
  extern __shared__ char dynsm[];
  int e = blockIdx.z;
  int cnt = g_cnt[e];
  int m0 = blockIdx.y*128;
  if (m0 >= cnt) return;
  int n0 = blockIdx.x*128;
  int off = g_off[e];
  const bf16* A = G1 ? g_qa : g_qh;
  const bf16* B = (G1 ? g_w1b : g_w2b) + (size_t)e*KSEG;

  uint32_t sbase = (uint32_t)__cvta_generic_to_shared(dynsm);

  int tid = threadIdx.x, wid = tid>>5, lane = tid&31;
  int wm = wid&3, wn = wid>>2;

  int lr = tid>>1;
  int lcb = (tid&1)*4;
  int swr = lr&7;
  int mA = m0 + lr;
  int szA = (mA < cnt) ? 16 : 0;
  const bf16* gA = A + (size_t)(off + min(mA, cnt-1))*KDIM;
  const bf16* gB = B + (size_t)(n0 + lr)*KDIM;
  uint32_t rowoff = (uint32_t)lr*128;

  uint32_t rAoff[2]; int rAsw[2];
  #pragma unroll
  for (int mf=0;mf<2;mf++){
    int rr = wm*32 + mf*16 + (lane&15);
    rAoff[mf] = (uint32_t)rr*128; rAsw[mf] = rr&7;
  }
  int aHi = lane>>4;
  uint32_t rBoff[4]; int rBsw[4];
  #pragma unroll
  for (int p=0;p<4;p++){
    int rr = wn*64 + p*16 + (lane&7) + ((lane>>4)<<3);
    rBoff[p] = (uint32_t)rr*128; rBsw[p] = rr&7;
  }
  int bHi = (lane>>3)&1;

  float c[2][8][4];
  #pragma unroll
  for (int i=0;i<2;i++)
    #pragma unroll
    for (int j=0;j<8;j++)
      #pragma unroll
      for (int k=0;k<4;k++) c[i][j][k]=0.f;

  const int NK = KDIM/64;
  // prologue: issue stages 0,1 (one commit group each)
  #pragma unroll
  for (int s=0;s<2;s++){
    size_t k0 = (size_t)s*64;
    uint32_t ab = sbase + s*32768;
    #pragma unroll
    for (int j=0;j<4;j++){
      int ch = lcb + j;
      uint32_t doff = rowoff + (uint32_t)((ch ^ swr)<<4);
      CP16(ab + doff,          gA + k0 + ch*8, szA);
      CP16(ab + 16384 + doff,  gB + k0 + ch*8, 16);
    }
    CP_COMMIT();
  }

  for (int kt=0; kt<NK; kt++){
    // wait for stage kt's group (allow 1 outstanding), then one barrier.
    CP_WAIT1();
    __syncthreads();
    // issue loads for stage kt+2 (its buffer was consumed at iter kt-1; the
    // barrier above guarantees all warps have finished reading it).
    if (kt+2 < NK){
      int s = (kt+2)%3;
      size_t k0 = (size_t)(kt+2)*64;
      uint32_t ab = sbase + s*32768;
      #pragma unroll
      for (int j=0;j<4;j++){
        int ch = lcb + j;
        uint32_t doff = rowoff + (uint32_t)((ch ^ swr)<<4);
        CP16(ab + doff,          gA + k0 + ch*8, szA);
        CP16(ab + 16384 + doff,  gB + k0 + ch*8, 16);
      }
    }
    CP_COMMIT();

    uint32_t ab = sbase + (kt%3)*32768;
    uint32_t bb = ab + 16384;
    #pragma unroll
    for (int ks=0;ks<4;ks++){
      int a[2][4];
      #pragma unroll
      for (int mf=0;mf<2;mf++){
        uint32_t addr = ab + rAoff[mf] + (uint32_t)(((2*ks + aHi) ^ rAsw[mf])<<4);
        LDSM4(a[mf][0],a[mf][1],a[mf][2],a[mf][3], addr);
      }
      int b[4][4];
      #pragma unroll
      for (int p=0;p<4;p++){
        uint32_t addr = bb + rBoff[p] + (uint32_t)(((2*ks + bHi) ^ rBsw[p])<<4);
        LDSM4(b[p][0],b[p][1],b[p][2],b[p][3], addr);
      }
      #pragma unroll
      for (int p=0;p<4;p++){
        #pragma unroll
        for (int half=0;half<2;half++){
          int nf = 2*p + half;
          int bb0 = b[p][half*2+0], bb1 = b[p][half*2+1];
          #pragma unroll
          for (int mf=0;mf<2;mf++){
            asm volatile(
              "mma.sync.aligned.m16n8k16.row.col.f32.bf16.bf16.f32 "
              "{%0,%1,%2,%3},{%4,%5,%6,%7},{%8,%9},{%0,%1,%2,%3};\n"
              : "+f"(c[mf][nf][0]),"+f"(c[mf][nf][1]),
                "+f"(c[mf][nf][2]),"+f"(c[mf][nf][3])
              : "r"(a[mf][0]),"r"(a[mf][1]),"r"(a[mf][2]),"r"(a[mf][3]),
                "r"(bb0),"r"(bb1));
          }
        }
      }
    }
  }

  // ---- epilogue ----
  int gid = lane>>2, tig = lane&3;
  float wmean = fmaxf(g_wsum[G1 ? e : 16+e]*(1.f/(float)KSEG), 1e-5f);
  #pragma unroll
  for (int mf=0;mf<2;mf++){
    #pragma unroll
    for (int h2=0;h2<2;h2++){
      int m = m0 + wm*32 + mf*16 + gid + h2*8;
      if (m >= cnt) continue;
      int arow = off + m;
      float sc = (G1 ? g_ra[arow] : g_rh[arow]) * wmean;
      if (G1){
        float* orow = g_h + (size_t)arow*NDIM;
        #pragma unroll
        for (int nf=0;nf<8;nf++){
          int col = n0 + wn*64 + nf*8 + 2*tig;
          float v0 = gelu_f(c[mf][nf][h2*2+0]*sc);
          float v1 = gelu_f(c[mf][nf][h2*2+1]*sc);
          *(float2*)(orow + col) = make_float2(v0,v1);
        }
      } else {
        sc *= g_awt[arow];
        int tok = g_atok[arow];
        float* orow = out + (size_t)tok*NDIM;
        #pragma unroll
        for (int nf=0;nf<8;nf++){
          int col = n0 + wn*64 + nf*8 + 2*tig;
          atomicAdd(orow + col,     c[mf][nf][h2*2+0]*sc);
          atomicAdd(orow + col + 1, c[mf][nf][h2*2+1]*sc);
        }
      }
    }
  }
}

extern "C" void kernel_launch(void* const* d_in, const int* in_sizes, int n_in,
                              void* d_out, int out_size){
  (void)in_sizes; (void)n_in;
  const float* x  = (const float*)d_in[0];
  const float* rw = (const float*)d_in[1];
  const float* w1 = (const float*)d_in[2];
  const float* g1 = (const float*)d_in[3];
  const float* w2 = (const float*)d_in[4];
  const float* g2 = (const float*)d_in[5];
  float* out = (float*)d_out;

  cudaFuncSetAttribute(k_gemm<true,KD,KF>,
                       cudaFuncAttributeMaxDynamicSharedMemorySize, DSMEM);
  cudaFuncSetAttribute(k_gemm<false,KF,KD>,
                       cudaFuncAttributeMaxDynamicSharedMemorySize, DSMEM);

  cudaMemsetAsync(out, 0, (size_t)out_size*sizeof(float));
  k_prep1<<<4608,256>>>(w1,w2,x,rw);
  k_mid<<<1,1024>>>(out + (size_t)out_size - 1);
  k_prep2<<<16384,256>>>(w1,w2,x,g1);
  k_gemm<true,KD,KF><<<dim3(KF/128, 32, KE),256,DSMEM>>>(nullptr);
  k_hq<<<KA,256>>>(g2);
  k_gemm<false,KF,KD><<<dim3(KD/128, 32, KE),256,DSMEM>>>(out);
}

// round 13
// speedup vs baseline: 1.0391x; 1.0260x over previous
#include <cuda_runtime.h>
#include <cuda_bf16.h>
#include <cstdint>

#define KE 16
#define KD 1024
#define KF 4096
#define KT 4096
#define KA 8192
#define KSEG 4194304  /* KF*KD elements per expert matrix */

typedef __nv_bfloat16 bf16;

// ---------------- device scratch (static; no allocations) ----------------
__device__ bf16   g_w1b[(size_t)KE*KSEG];   // 128 MB ternary (exact in bf16)
__device__ bf16   g_w2b[(size_t)KE*KSEG];   // 128 MB
__device__ bf16   g_qa[(size_t)KA*KD];      // 16 MB quantized activations (gemm1 A)
__device__ bf16   g_qh[(size_t)KA*KF];      // 64 MB quantized hidden (gemm2 A)
__device__ float  g_h[(size_t)KA*KF];       // 128 MB fp32 hidden (gelu output)
__device__ float  g_wpart[4096];            // wsum partials (32 segs x 128 blocks)
__device__ float  g_wsum[32];
__device__ float  g_probs[KT*16];           // per-token softmax probs
__device__ float  g_ra[KA];
__device__ float  g_rh[KA];
__device__ float  g_ir[KT];
__device__ int    g_te[KT*2];
__device__ float  g_tw[KT*2];
__device__ int    g_cnt[KE];
__device__ int    g_off[KE];
__device__ int    g_atok[KA];
__device__ int    g_aexp[KA];
__device__ float  g_awt[KA];
__device__ int    g_nmt;                    // number of active m-tiles
__device__ int    g_mtl[128];               // tile list: (e<<8)|mtile

__device__ __forceinline__ float rsqrt_acc(float v){
  float r = rsqrtf(v);
  r = r*(1.5f - 0.5f*v*r*r);
  return r;
}
__device__ __forceinline__ float gelu_f(float v){
  float u = 0.7978845608028654f*(v + 0.044715f*v*v*v);
  u = fminf(fmaxf(u,-15.f),15.f);
  float ez = __expf(2.f*u);
  return 0.5f*v*(1.f + (ez-1.f)/(ez+1.f));
}

// ternary quantize 16384 fp32 elems -> bf16, one block of 256 threads
__device__ __forceinline__ void wquant_chunk(const float* __restrict__ src,
                                             bf16* __restrict__ dst, int seg){
  float mean = g_wsum[seg] * (1.f/(float)KSEG);
  float sc = 1.f / fmaxf(mean, 1e-5f);
  const float4* s4 = (const float4*)src;
  ushort4* d4 = (ushort4*)dst;
  #pragma unroll 4
  for (int i=threadIdx.x; i<4096; i+=256){
    float4 v = s4[i];
    bf16 b0 = __float2bfloat16(fminf(fmaxf(rintf(v.x*sc),-1.f),1.f));
    bf16 b1 = __float2bfloat16(fminf(fmaxf(rintf(v.y*sc),-1.f),1.f));
    bf16 b2 = __float2bfloat16(fminf(fmaxf(rintf(v.z*sc),-1.f),1.f));
    bf16 b3 = __float2bfloat16(fminf(fmaxf(rintf(v.w*sc),-1.f),1.f));
    ushort4 u;
    u.x = *(unsigned short*)&b0; u.y = *(unsigned short*)&b1;
    u.z = *(unsigned short*)&b2; u.w = *(unsigned short*)&b3;
    d4[i] = u;
  }
}

// ======== prep1: wsum partials (4096 blocks) interleaved 8:1 with router ========
__global__ __launch_bounds__(256) void k_prep1(const float* __restrict__ w1,
                                               const float* __restrict__ w2,
                                               const float* __restrict__ x,
                                               const float* __restrict__ rw){
  __shared__ float sm[256];
  int idx = blockIdx.x;
  int r = idx % 9;
  if (r < 8){
    int b = (idx/9)*8 + r;              // 0..4095
    int seg = b >> 7;                   // 0..31
    int sub = b & 127;
    const float* base = (seg<16) ? (w1 + (size_t)seg*KSEG)
                                 : (w2 + (size_t)(seg-16)*KSEG);
    const float4* p = (const float4*)(base + (size_t)sub*(KSEG/128));
    float s=0.f;
    for (int i=threadIdx.x; i<KSEG/512; i+=256){
      float4 v = p[i];
      s += fabsf(v.x)+fabsf(v.y)+fabsf(v.z)+fabsf(v.w);
    }
    sm[threadIdx.x]=s; __syncthreads();
    for (int st=128; st>0; st>>=1){
      if (threadIdx.x<st) sm[threadIdx.x]+=sm[threadIdx.x+st];
      __syncthreads();
    }
    if (threadIdx.x==0) g_wpart[b]=sm[0];
  } else {
    // router: 8 warps per block, one token per warp
    int rb = idx/9;                     // 0..511
    int wid = threadIdx.x>>5, lane = threadIdx.x&31;
    int t = rb*8 + wid;
    const float* xr = x + (size_t)t*KD;
    float acc[16]; float ss=0.f;
    #pragma unroll
    for (int e=0;e<16;e++) acc[e]=0.f;
    #pragma unroll 1
    for (int j=0;j<8;j++){
      int k = j*128 + lane*4;
      float4 xv = *(const float4*)(xr + k);
      ss += xv.x*xv.x+xv.y*xv.y+xv.z*xv.z+xv.w*xv.w;
      #pragma unroll
      for (int e=0;e<16;e++){
        float4 wv = __ldg((const float4*)(rw + e*KD + k));
        acc[e] += xv.x*wv.x+xv.y*wv.y+xv.z*wv.z+xv.w*wv.w;
      }
    }
    #pragma unroll
    for (int o=16;o>0;o>>=1){
      ss += __shfl_xor_sync(~0u, ss, o);
      #pragma unroll
      for (int e=0;e<16;e++) acc[e] += __shfl_xor_sync(~0u, acc[e], o);
    }
    if (lane==0){
      g_ir[t] = rsqrt_acc(ss*(1.f/(float)KD) + 1e-6f);
      float m = acc[0];
      #pragma unroll
      for (int e=1;e<16;e++) m = fmaxf(m, acc[e]);
      float p[16]; float Z=0.f;
      #pragma unroll
      for (int e=0;e<16;e++){ p[e]=__expf(acc[e]-m); Z+=p[e]; }
      float invZ = 1.f/Z;
      #pragma unroll
      for (int e=0;e<16;e++){ p[e]*=invZ; g_probs[t*16+e]=p[e]; }
      int i0=0;
      for (int e=1;e<16;e++) if (p[e]>p[i0]) i0=e;
      int i1=(i0==0)?1:0;
      for (int e=0;e<16;e++){ if (e!=i0 && p[e]>p[i1]) i1=e; }
      float s2 = p[i0]+p[i1]+1e-8f;
      g_te[2*t]=i0; g_te[2*t+1]=i1;
      g_tw[2*t]=p[i0]/s2; g_tw[2*t+1]=p[i1]/s2;
    }
  }
}

// ======== mid: reduce wsum, aux loss, offsets, tile list, scatter ========
__global__ void k_mid(float* out_aux){
  __shared__ float sps[16];
  __shared__ int scnt[16], soff[16], scur[16];
  int tid = threadIdx.x;            // 1024
  if (tid<16){ sps[tid]=0.f; scnt[tid]=0; scur[tid]=0; }
  if (tid<32){
    float s=0.f;
    for (int i=0;i<128;i++) s += g_wpart[tid*128+i];
    g_wsum[tid]=s;
  }
  __syncthreads();
  {
    float lp[16];
    #pragma unroll
    for (int e=0;e<16;e++) lp[e]=0.f;
    for (int t=tid;t<KT;t+=1024){
      #pragma unroll
      for (int e=0;e<16;e++) lp[e] += g_probs[t*16+e];
    }
    #pragma unroll
    for (int e=0;e<16;e++) atomicAdd(&sps[e], lp[e]);
  }
  for (int i=tid;i<KA;i+=1024) atomicAdd(&scnt[g_te[i]], 1);
  __syncthreads();
  if (tid==0){
    int off=0;
    float aux=0.f;
    int nt=0;
    for (int e=0;e<16;e++){
      soff[e]=off; g_off[e]=off; g_cnt[e]=scnt[e]; off+=scnt[e];
      aux += ((float)scnt[e]/(float)KA) * (sps[e]/(float)KT);
      int nm = (scnt[e]+127)>>7;
      for (int m=0;m<nm;m++) g_mtl[nt++] = (e<<8)|m;
    }
    g_nmt = nt;
    *out_aux = 16.f*aux;
  }
  __syncthreads();
  for (int t=tid;t<KT;t+=1024){
    #pragma unroll
    for (int s=0;s<2;s++){
      int e = g_te[2*t+s];
      int pos = soff[e] + atomicAdd(&scur[e],1);
      g_atok[pos]=t; g_aexp[pos]=e; g_awt[pos]=g_tw[2*t+s];
    }
  }
}

// ======== prep2: wquant(w1) [4096] + wquant(w2) [4096] + qa [8192] ========
__global__ __launch_bounds__(256) void k_prep2(const float* __restrict__ w1,
                                               const float* __restrict__ w2,
                                               const float* __restrict__ x,
                                               const float* __restrict__ g1){
  __shared__ float sm[256];
  int b = blockIdx.x;
  if (b < 4096){
    wquant_chunk(w1 + (size_t)b*16384, g_w1b + (size_t)b*16384, b>>8);
    return;
  }
  if (b < 8192){
    int q = b - 4096;
    wquant_chunk(w2 + (size_t)q*16384, g_w2b + (size_t)q*16384, 16 + (q>>8));
    return;
  }
  int a = b - 8192;
  int tid = threadIdx.x;
  int t = g_atok[a], e = g_aexp[a];
  float ir = g_ir[t];
  float4 xv = *(const float4*)(x  + (size_t)t*KD + tid*4);
  float4 gv = *(const float4*)(g1 + (size_t)e*KD + tid*4);
  float4 y = make_float4(xv.x*gv.x*ir, xv.y*gv.y*ir, xv.z*gv.z*ir, xv.w*gv.w*ir);
  float mx = fmaxf(fmaxf(fabsf(y.x),fabsf(y.y)),fmaxf(fabsf(y.z),fabsf(y.w)));
  sm[tid]=mx; __syncthreads();
  for (int st=128;st>0;st>>=1){
    if (tid<st) sm[tid]=fmaxf(sm[tid],sm[tid+st]);
    __syncthreads();
  }
  float mv = fmaxf(sm[0],1e-5f);
  float sc = 127.f/mv;
  if (tid==0) g_ra[a] = mv*(1.f/127.f);
  float q0=fminf(fmaxf(rintf(y.x*sc),-128.f),127.f);
  float q1=fminf(fmaxf(rintf(y.y*sc),-128.f),127.f);
  float q2=fminf(fmaxf(rintf(y.z*sc),-128.f),127.f);
  float q3=fminf(fmaxf(rintf(y.w*sc),-128.f),127.f);
  bf16 b0=__float2bfloat16(q0), b1=__float2bfloat16(q1);
  bf16 b2=__float2bfloat16(q2), b3=__float2bfloat16(q3);
  ushort4 u;
  u.x=*(unsigned short*)&b0; u.y=*(unsigned short*)&b1;
  u.z=*(unsigned short*)&b2; u.w=*(unsigned short*)&b3;
  *(ushort4*)(g_qa + (size_t)a*KD + tid*4) = u;
}

// ======== rmsnorm(h,g2[e]) + act_quant -> qh ========
__global__ void k_hq(const float* __restrict__ g2){
  int a = blockIdx.x; int tid=threadIdx.x;
  int e = g_aexp[a];
  const float* hr = g_h + (size_t)a*KF;
  float4 y[4]; float ss=0.f, mx=0.f;
  #pragma unroll
  for (int j=0;j<4;j++){
    int k = tid*4 + j*1024;
    float4 hv = *(const float4*)(hr + k);
    float4 gv = *(const float4*)(g2 + (size_t)e*KF + k);
    ss += hv.x*hv.x+hv.y*hv.y+hv.z*hv.z+hv.w*hv.w;
    y[j] = make_float4(hv.x*gv.x, hv.y*gv.y, hv.z*gv.z, hv.w*gv.w);
    mx = fmaxf(mx, fmaxf(fmaxf(fabsf(y[j].x),fabsf(y[j].y)),
                         fmaxf(fabsf(y[j].z),fabsf(y[j].w))));
  }
  __shared__ float sms[256], smm[256];
  sms[tid]=ss; smm[tid]=mx; __syncthreads();
  for (int st=128;st>0;st>>=1){
    if (tid<st){ sms[tid]+=sms[tid+st]; smm[tid]=fmaxf(smm[tid],smm[tid+st]); }
    __syncthreads();
  }
  float ir = rsqrt_acc(sms[0]*(1.f/(float)KF)+1e-6f);
  float my = fmaxf(smm[0]*ir, 1e-5f);
  float sc = 127.f/my;
  if (tid==0) g_rh[a] = my*(1.f/127.f);
  float f = ir*sc;
  #pragma unroll
  for (int j=0;j<4;j++){
    int k = tid*4 + j*1024;
    float q0=fminf(fmaxf(rintf(y[j].x*f),-128.f),127.f);
    float q1=fminf(fmaxf(rintf(y[j].y*f),-128.f),127.f);
    float q2=fminf(fmaxf(rintf(y[j].z*f),-128.f),127.f);
    float q3=fminf(fmaxf(rintf(y[j].w*f),-128.f),127.f);
    bf16 b0=__float2bfloat16(q0), b1=__float2bfloat16(q1);
    bf16 b2=__float2bfloat16(q2), b3=__float2bfloat16(q3);
    ushort4 u;
    u.x=*(unsigned short*)&b0; u.y=*(unsigned short*)&b1;
    u.z=*(unsigned short*)&b2; u.w=*(unsigned short*)&b3;
    *(ushort4*)(g_qh + (size_t)a*KF + k)=u;
  }
}

// ======== pipelined bf16 HMMA GEMM, single barrier per K-step, tile list ========
#define CP16(dst, src, sz) \
  asm volatile("cp.async.cg.shared.global [%0],[%1],16,%2;\n"::"r"(dst),"l"(src),"r"(sz))
#define CP_COMMIT() asm volatile("cp.async.commit_group;\n"::)
#define CP_WAIT1()  asm volatile("cp.async.wait_group 1;\n"::: "memory")
#define LDSM4(r0,r1,r2,r3,addr) \
  asm volatile("ldmatrix.sync.aligned.m8n8.x4.shared.b16 {%0,%1,%2,%3},[%4];\n" \
    : "=r"(r0),"=r"(r1),"=r"(r2),"=r"(r3) : "r"(addr))

#define DSMEM (3*32768)
#define MAXMT 80

template<bool G1, int KDIM, int NDIM>
__global__ __launch_bounds__(256,2) void k_gemm(float* __restrict__ out){
  extern __shared__ char dynsm[];
  if ((int)blockIdx.y >= g_nmt) return;
  int tl = g_mtl[blockIdx.y];
  int e = tl>>8;
  int m0 = (tl&255)*128;
  int cnt = g_cnt[e];
  int n0 = blockIdx.x*128;
  int off = g_off[e];
  const bf16* A = G1 ? g_qa : g_qh;
  const bf16* B = (G1 ? g_w1b : g_w2b) + (size_t)e*KSEG;

  uint32_t sbase = (uint32_t)__cvta_generic_to_shared(dynsm);

  int tid = threadIdx.x, wid = tid>>5, lane = tid&31;
  int wm = wid&3, wn = wid>>2;

  int lr = tid>>1;
  int lcb = (tid&1)*4;
  int swr = lr&7;
  int mA = m0 + lr;
  int szA = (mA < cnt) ? 16 : 0;
  const bf16* gA = A + (size_t)(off + min(mA, cnt-1))*KDIM;
  const bf16* gB = B + (size_t)(n0 + lr)*KDIM;
  uint32_t rowoff = (uint32_t)lr*128;

  uint32_t rAoff[2]; int rAsw[2];
  #pragma unroll
  for (int mf=0;mf<2;mf++){
    int rr = wm*32 + mf*16 + (lane&15);
    rAoff[mf] = (uint32_t)rr*128; rAsw[mf] = rr&7;
  }
  int aHi = lane>>4;
  uint32_t rBoff[4]; int rBsw[4];
  #pragma unroll
  for (int p=0;p<4;p++){
    int rr = wn*64 + p*16 + (lane&7) + ((lane>>4)<<3);
    rBoff[p] = (uint32_t)rr*128; rBsw[p] = rr&7;
  }
  int bHi = (lane>>3)&1;

  float c[2][8][4];
  #pragma unroll
  for (int i=0;i<2;i++)
    #pragma unroll
    for (int j=0;j<8;j++)
      #pragma unroll
      for (int k=0;k<4;k++) c[i][j][k]=0.f;

  const int NK = KDIM/64;
  #pragma unroll
  for (int s=0;s<2;s++){
    size_t k0 = (size_t)s*64;
    uint32_t ab = sbase + s*32768;
    #pragma unroll
    for (int j=0;j<4;j++){
      int ch = lcb + j;
      uint32_t doff = rowoff + (uint32_t)((ch ^ swr)<<4);
      CP16(ab + doff,          gA + k0 + ch*8, szA);
      CP16(ab + 16384 + doff,  gB + k0 + ch*8, 16);
    }
    CP_COMMIT();
  }

  for (int kt=0; kt<NK; kt++){
    CP_WAIT1();
    __syncthreads();
    if (kt+2 < NK){
      int s = (kt+2)%3;
      size_t k0 = (size_t)(kt+2)*64;
      uint32_t ab = sbase + s*32768;
      #pragma unroll
      for (int j=0;j<4;j++){
        int ch = lcb + j;
        uint32_t doff = rowoff + (uint32_t)((ch ^ swr)<<4);
        CP16(ab + doff,          gA + k0 + ch*8, szA);
        CP16(ab + 16384 + doff,  gB + k0 + ch*8, 16);
      }
    }
    CP_COMMIT();

    uint32_t ab = sbase + (kt%3)*32768;
    uint32_t bb = ab + 16384;
    #pragma unroll
    for (int ks=0;ks<4;ks++){
      int a[2][4];
      #pragma unroll
      for (int mf=0;mf<2;mf++){
        uint32_t addr = ab + rAoff[mf] + (uint32_t)(((2*ks + aHi) ^ rAsw[mf])<<4);
        LDSM4(a[mf][0],a[mf][1],a[mf][2],a[mf][3], addr);
      }
      int b[4][4];
      #pragma unroll
      for (int p=0;p<4;p++){
        uint32_t addr = bb + rBoff[p] + (uint32_t)(((2*ks + bHi) ^ rBsw[p])<<4);
        LDSM4(b[p][0],b[p][1],b[p][2],b[p][3], addr);
      }
      #pragma unroll
      for (int p=0;p<4;p++){
        #pragma unroll
        for (int half=0;half<2;half++){
          int nf = 2*p + half;
          int bb0 = b[p][half*2+0], bb1 = b[p][half*2+1];
          #pragma unroll
          for (int mf=0;mf<2;mf++){
            asm volatile(
              "mma.sync.aligned.m16n8k16.row.col.f32.bf16.bf16.f32 "
              "{%0,%1,%2,%3},{%4,%5,%6,%7},{%8,%9},{%0,%1,%2,%3};\n"
              : "+f"(c[mf][nf][0]),"+f"(c[mf][nf][1]),
                "+f"(c[mf][nf][2]),"+f"(c[mf][nf][3])
              : "r"(a[mf][0]),"r"(a[mf][1]),"r"(a[mf][2]),"r"(a[mf][3]),
                "r"(bb0),"r"(bb1));
          }
        }
      }
    }
  }

  // ---- epilogue ----
  int gid = lane>>2, tig = lane&3;
  float wmean = fmaxf(g_wsum[G1 ? e : 16+e]*(1.f/(float)KSEG), 1e-5f);
  #pragma unroll
  for (int mf=0;mf<2;mf++){
    #pragma unroll
    for (int h2=0;h2<2;h2++){
      int m = m0 + wm*32 + mf*16 + gid + h2*8;
      if (m >= cnt) continue;
      int arow = off + m;
      float sc = (G1 ? g_ra[arow] : g_rh[arow]) * wmean;
      if (G1){
        float* orow = g_h + (size_t)arow*NDIM;
        #pragma unroll
        for (int nf=0;nf<8;nf++){
          int col = n0 + wn*64 + nf*8 + 2*tig;
          float v0 = gelu_f(c[mf][nf][h2*2+0]*sc);
          float v1 = gelu_f(c[mf][nf][h2*2+1]*sc);
          *(float2*)(orow + col) = make_float2(v0,v1);
        }
      } else {
        sc *= g_awt[arow];
        int tok = g_atok[arow];
        float* orow = out + (size_t)tok*NDIM;
        #pragma unroll
        for (int nf=0;nf<8;nf++){
          int col = n0 + wn*64 + nf*8 + 2*tig;
          atomicAdd(orow + col,     c[mf][nf][h2*2+0]*sc);
          atomicAdd(orow + col + 1, c[mf][nf][h2*2+1]*sc);
        }
      }
    }
  }
}

extern "C" void kernel_launch(void* const* d_in, const int* in_sizes, int n_in,
                              void* d_out, int out_size){
  (void)in_sizes; (void)n_in;
  const float* x  = (const float*)d_in[0];
  const float* rw = (const float*)d_in[1];
  const float* w1 = (const float*)d_in[2];
  const float* g1 = (const float*)d_in[3];
  const float* w2 = (const float*)d_in[4];
  const float* g2 = (const float*)d_in[5];
  float* out = (float*)d_out;

  cudaFuncSetAttribute(k_gemm<true,KD,KF>,
                       cudaFuncAttributeMaxDynamicSharedMemorySize, DSMEM);
  cudaFuncSetAttribute(k_gemm<false,KF,KD>,
                       cudaFuncAttributeMaxDynamicSharedMemorySize, DSMEM);

  cudaMemsetAsync(out, 0, (size_t)out_size*sizeof(float));
  k_prep1<<<4608,256>>>(w1,w2,x,rw);
  k_mid<<<1,1024>>>(out + (size_t)out_size - 1);
  k_prep2<<<16384,256>>>(w1,w2,x,g1);
  k_gemm<true,KD,KF><<<dim3(KF/128, MAXMT),256,DSMEM>>>(nullptr);
  k_hq<<<KA,256>>>(g2);
  k_gemm<false,KF,KD><<<dim3(KD/128, MAXMT),256,DSMEM>>>(out);
}